// round 16
// baseline (speedup 1.0000x reference)
#include <cuda_runtime.h>
#include <cuda_bf16.h>

#define START_ID 62
#define PAD_ID   63
#define BATCH    512
#define SEQ      512
#define LBL      64
#define SEGW     64
#define OV       8    // burn-in steps; interior window = 72 = 9 groups of 8

typedef unsigned long long ull;

__device__ int    g_off[BATCH + 1];  // prefix sum of ceil(len/64)
__device__ float4 g_E[1024];         // exp(T), lane-coalesced packing

__device__ __forceinline__ float ex2f_(float x) {
    float y; asm("ex2.approx.f32 %0, %1;" : "=f"(y) : "f"(x)); return y;
}
__device__ __forceinline__ float lg2f_(float x) {
    float y; asm("lg2.approx.f32 %0, %1;" : "=f"(y) : "f"(x)); return y;
}
__device__ __forceinline__ ull fma2_(ull a, ull b, ull c) {
    ull d; asm("fma.rn.f32x2 %0, %1, %2, %3;" : "=l"(d) : "l"(a), "l"(b), "l"(c)); return d;
}
__device__ __forceinline__ ull add2_(ull a, ull b) {
    ull d; asm("add.rn.f32x2 %0, %1, %2;" : "=l"(d) : "l"(a), "l"(b)); return d;
}
__device__ __forceinline__ void unpack2_(ull v, float& lo, float& hi) {
    asm("mov.b64 {%0, %1}, %2;" : "=f"(lo), "=f"(hi) : "l"(v));
}

// Compiler-only ordering barrier: the loop is warp-convergent and the
// STS->LDS hazard is cross-lane aliased (ptxas must keep program order;
// same-warp LSU is in-order), so no WARPSYNC instruction is needed.
#define CBAR() asm volatile("" ::: "memory")

#define MATVEC(BUF)                                                         \
    const ulonglong2* p4_ = (const ulonglong2*)sp[w][BUF];                  \
    ull a0_=0, a1_=0, b0_=0, b1_=0;                                         \
    _Pragma("unroll")                                                       \
    for (int q = 0; q < 16; ++q) {                                          \
        ulonglong2 v_ = p4_[q];                                             \
        a0_ = fma2_(v_.x, EA[2*q],     a0_);                                \
        a1_ = fma2_(v_.y, EA[2*q + 1], a1_);                                \
        b0_ = fma2_(v_.x, EB[2*q],     b0_);                                \
        b1_ = fma2_(v_.y, EB[2*q + 1], b1_);                                \
    }                                                                       \
    float ax_, ay_, bx_, by_;                                               \
    unpack2_(add2_(a0_, a1_), ax_, ay_);                                    \
    unpack2_(add2_(b0_, b1_), bx_, by_);

// FAST step (interior segment): no clamps, no freezes, no compares.
#define STEPF(SLOT, BUF, RENORM) do {                                       \
    float ex_ = er##SLOT.x, ey_ = er##SLOT.y;                               \
    er##SLOT = ts2[(size_t)(s0 + u + 4) * 32 + tid];                        \
    float c0_, c1_;                                                         \
    if (RENORM) {                                                           \
        float p0_ = __shfl_sync(FULL, Px, 0);                               \
        float Kp_ = lg2f_(p0_);                                             \
        c0_ = ex2f_(fmaf(ex_, INV_LN2, -Kp_));                              \
        c1_ = ex2f_(fmaf(ey_, INV_LN2, -Kp_));                              \
        Mcur += Kp_;                                                        \
    } else {                                                                \
        c0_ = ex2f_(ex_ * INV_LN2);                                         \
        c1_ = ex2f_(ey_ * INV_LN2);                                         \
    }                                                                       \
    CBAR();                                                                 \
    { MATVEC(BUF);                                                          \
      Px = (ax_ + ay_) * c0_;  Py = (bx_ + by_) * c1_; }                    \
    ((float2*)sp[w][(BUF) ^ 1])[tid] = make_float2(Px, Py);                 \
    CBAR();                                                                 \
    ++u;                                                                    \
} while (0)

// SLOW step (last segment): clamped prefetch + predicated freeze for pad.
#define STEPS(SLOT, BUF, RENORM) do {                                       \
    float ex_ = er##SLOT.x, ey_ = er##SLOT.y;                               \
    int tt_ = s0 + u + 4; if (tt_ > e) tt_ = e;                             \
    er##SLOT = ts2[(size_t)tt_ * 32 + tid];                                 \
    const bool gg_ = (u <= n);                                              \
    float c0_, c1_;                                                         \
    if (RENORM) {                                                           \
        float p0_ = __shfl_sync(FULL, Px, 0);                               \
        float Kp_ = lg2f_(p0_);                                             \
        c0_ = ex2f_(fmaf(ex_, INV_LN2, -Kp_));                              \
        c1_ = ex2f_(fmaf(ey_, INV_LN2, -Kp_));                              \
        Mcur += gg_ ? Kp_ : 0.0f;                                           \
    } else {                                                                \
        c0_ = ex2f_(ex_ * INV_LN2);                                         \
        c1_ = ex2f_(ey_ * INV_LN2);                                         \
    }                                                                       \
    CBAR();                                                                 \
    { MATVEC(BUF);                                                          \
      float nPx_ = (ax_ + ay_) * c0_;                                       \
      float nPy_ = (bx_ + by_) * c1_;                                       \
      Px = gg_ ? nPx_ : Px;  Py = gg_ ? nPy_ : Py; }                        \
    ((float2*)sp[w][(BUF) ^ 1])[tid] = make_float2(Px, Py);                 \
    CBAR();                                                                 \
    ++u;                                                                    \
} while (0)

#define GROUP8(S) do {                                                      \
    S(0, 0, 1); S(1, 1, 0); S(2, 0, 0); S(3, 1, 0);                         \
    S(0, 0, 0); S(1, 1, 0); S(2, 0, 0); S(3, 1, 0);                         \
} while (0)

// ---- kernel A: prefix-scan of active-segment counts + exp(T) table ----
// g_E[q*32 + l] = (E[2q][2l], E[2q+1][2l], E[2q][2l+1], E[2q+1][2l+1])
__global__ void seg_scan_kernel(const void* __restrict__ lengths_raw,
                                const float* __restrict__ Tm) {
    __shared__ int buf[BATCH];
    const int t = threadIdx.x;
    const int* l32 = (const int*)lengths_raw;
    const bool is64 = (l32[1] == 0);
    int len = is64 ? (int)(((const long long*)lengths_raw)[t]) : l32[t];
    buf[t] = (len + SEGW - 1) >> 6;              // ceil(len/64), >=1

    // E table: 1024 float4 entries, 2 per thread
    #pragma unroll
    for (int r = 0; r < 2; ++r) {
        int idx = t + r * BATCH;                 // 0..1023
        int q = idx >> 5, l = idx & 31;
        float4 v;
        v.x = __expf(Tm[(2*q)     * LBL + 2*l]);
        v.y = __expf(Tm[(2*q + 1) * LBL + 2*l]);
        v.z = __expf(Tm[(2*q)     * LBL + 2*l + 1]);
        v.w = __expf(Tm[(2*q + 1) * LBL + 2*l + 1]);
        g_E[idx] = v;
    }

    __syncthreads();
    for (int d = 1; d < BATCH; d <<= 1) {
        int x = (t >= d) ? buf[t - d] : 0;
        __syncthreads();
        buf[t] += x;
        __syncthreads();
    }
    g_off[t + 1] = buf[t];
    if (t == 0) g_off[0] = 0;
}

// ---- kernel B: compacted work list — global warp W -> (batch b, seg) ----
__global__ __launch_bounds__(128, 3) void crf_loss_kernel(
    const float* __restrict__ ts,          // [B, S, L]
    const float* __restrict__ Tm,          // [L, L]
    const void*  __restrict__ labels_raw,  // [B, S] int32 or int64
    const void*  __restrict__ lengths_raw, // [B]    int32 or int64
    float* __restrict__ out)
{
    const int w   = threadIdx.x >> 5;
    const int tid = threadIdx.x & 31;            // lane: labels 2*tid, 2*tid+1
    const unsigned FULL = 0xffffffffu;

    __shared__ __align__(16) float sp[4][2][LBL];
    __shared__ int soff[BATCH + 1];

    const int total = g_off[BATCH];
    const int Wbase = blockIdx.x << 2;
    if (Wbase >= total) return;                  // whole-CTA early exit

    for (int i = threadIdx.x; i <= BATCH; i += 128) soff[i] = g_off[i];
    __syncthreads();                             // last CTA-wide sync

    const int W = Wbase + w;
    if (W >= total) return;                      // partial CTA: warp exit

    // binary search: b with soff[b] <= W < soff[b+1]
    int blo = 0, bhi = BATCH;
    while (bhi - blo > 1) {
        int mid = (blo + bhi) >> 1;
        if (soff[mid] <= W) blo = mid; else bhi = mid;
    }
    const int b   = blo;
    const int seg = W - soff[b];

    const float INV_LN2 = 1.44269504088896340736f;
    const float LN2     = 0.69314718055994530942f;

    const int* l32 = (const int*)lengths_raw;
    const bool is64 = (l32[1] == 0);
    int len;
    if (is64) len = (int)(((const long long*)lengths_raw)[b]);
    else      len = l32[b];

    const int  tauB = seg * SEGW;
    const int  tauE = tauB + SEGW;
    const bool last = (len <= tauE);

    const float* tsb = ts + (size_t)b * SEQ * LBL;
    const float2* ts2 = (const float2*)tsb;

    // ---- E from the precomputed table: 32 coalesced LDG.128 per lane ----
    ull EA[32], EB[32];
    {
        const ulonglong2* Eg = (const ulonglong2*)g_E;
        #pragma unroll
        for (int q = 0; q < 32; ++q) {
            ulonglong2 v = Eg[q * 32 + tid];
            EA[q] = v.x;                          // (E[2q][2t], E[2q+1][2t])
            EB[q] = v.y;                          // (E[2q][2t+1], E[2q+1][2t+1])
        }
    }

    const int e  = last ? (len - 1) : tauE;
    const int s0 = (seg == 0) ? 0 : (tauB - OV);
    const int n  = e - s0;                       // interior: 72 (seg>0) or 64
    const int ng = (n + 7) >> 3;

    // ---- init A at s0 (true init iff seg0) ----
    float2 a0v = ts2[(size_t)s0 * 32 + tid];
    float A0, A1;
    if (seg == 0) {
        float2 tv = ((const float2*)(Tm + START_ID * LBL))[tid];
        A0 = (a0v.x + tv.x) * INV_LN2;
        A1 = (a0v.y + tv.y) * INV_LN2;
    } else {
        A0 = a0v.x * INV_LN2;
        A1 = a0v.y * INV_LN2;
    }
    float Mcur = __shfl_sync(FULL, A0, 0);
    float Px = ex2f_(A0 - Mcur);
    float Py = ex2f_(A1 - Mcur);
    ((float2*)sp[w][0])[tid] = make_float2(Px, Py);
    CBAR();

    float Msave = Mcur, Psave = Px;

    // ---- named-register prefetch ring (depth 4) ----
    float2 er0, er1, er2, er3;
    {
        int t1 = s0 + 1; if (t1 > e) t1 = e;
        int t2 = s0 + 2; if (t2 > e) t2 = e;
        int t3 = s0 + 3; if (t3 > e) t3 = e;
        int t4 = s0 + 4; if (t4 > e) t4 = e;
        er0 = ts2[(size_t)t1 * 32 + tid];
        er1 = ts2[(size_t)t2 * 32 + tid];
        er2 = ts2[(size_t)t3 * 32 + tid];
        er3 = ts2[(size_t)t4 * 32 + tid];
    }

    int u = 1;
    if (ng > 0) {
        if (!last) {
            GROUP8(STEPF);
            if (seg) { Msave = Mcur; Psave = Px; }   // u==8==OV: V(tauB) snapshot
            for (int g = 1; g < ng; ++g) GROUP8(STEPF);
        } else {
            GROUP8(STEPS);
            if (seg) { Msave = Mcur; Psave = Px; }
            for (int g = 1; g < ng; ++g) GROUP8(STEPS);
        }
    }

    // ---- segment contribution (log2 units) ----
    float fwd;
    if (last) {
        float tp0 = Tm[(2*tid)     * LBL + PAD_ID] * INV_LN2;
        float tp1 = Tm[(2*tid + 1) * LBL + PAD_ID] * INV_LN2;
        float z0 = Mcur + lg2f_(Px) + tp0;
        float z1 = Mcur + lg2f_(Py) + tp1;
        float m = fmaxf(z0, z1);
        #pragma unroll
        for (int o = 16; o > 0; o >>= 1)
            m = fmaxf(m, __shfl_xor_sync(FULL, m, o));
        float sv = ex2f_(z0 - m) + ex2f_(z1 - m);
        #pragma unroll
        for (int o = 16; o > 0; o >>= 1)
            sv += __shfl_xor_sync(FULL, sv, o);
        fwd = m + lg2f_(sv);
    } else {
        float pe0 = __shfl_sync(FULL, Px, 0);
        fwd = Mcur + lg2f_(pe0);                 // +V(tauE)
    }
    if (seg > 0) {
        float ps0 = __shfl_sync(FULL, Psave, 0);
        fwd -= (Msave + lg2f_(ps0));             // -V(tauB)
    }

    // ---- gold path score over [tauB, min(tauE, len)) ----
    const int hi = last ? len : tauE;
    float gsum = 0.0f;
    int last_label = 0;
    if (is64) {
        const long long* lab = (const long long*)labels_raw + (size_t)b * SEQ;
        for (int t = tauB + tid; t < hi; t += 32) {
            int lt = (int)lab[t];
            int pt = (t == 0) ? START_ID : (int)lab[t - 1];
            gsum += Tm[pt * LBL + lt] + tsb[(size_t)t * LBL + lt];
        }
        if (last && tid == 0) last_label = (int)lab[len - 1];
    } else {
        const int* lab = (const int*)labels_raw + (size_t)b * SEQ;
        for (int t = tauB + tid; t < hi; t += 32) {
            int lt = lab[t];
            int pt = (t == 0) ? START_ID : lab[t - 1];
            gsum += Tm[pt * LBL + lt] + tsb[(size_t)t * LBL + lt];
        }
        if (last && tid == 0) last_label = lab[len - 1];
    }
    #pragma unroll
    for (int o = 16; o > 0; o >>= 1)
        gsum += __shfl_xor_sync(FULL, gsum, o);

    if (tid == 0) {
        float gold = gsum + (last ? Tm[last_label * LBL + PAD_ID] : 0.0f);
        atomicAdd(out, (fwd * LN2 - gold) * (1.0f / (float)BATCH));
    }
}

extern "C" void kernel_launch(void* const* d_in, const int* in_sizes, int n_in,
                              void* d_out, int out_size)
{
    const float* ts      = (const float*)d_in[0];
    const float* Tm      = (const float*)d_in[1];
    const void*  labels  = d_in[2];
    const void*  lengths = d_in[3];
    float* out = (float*)d_out;

    cudaMemsetAsync(out, 0, sizeof(float));
    seg_scan_kernel<<<1, BATCH>>>(lengths, Tm);
    // max possible works = BATCH * 8; trailing CTAs exit immediately
    crf_loss_kernel<<<(BATCH * 8) / 4, 128>>>(ts, Tm, labels, lengths, out);
}

// round 17
// speedup vs baseline: 1.0906x; 1.0906x over previous
#include <cuda_runtime.h>
#include <cuda_bf16.h>

#define START_ID 62
#define PAD_ID   63
#define BATCH    512
#define SEQ      512
#define LBL      64
#define SEGW     64
#define OV       8    // burn-in steps; interior window = 72 = 9 groups of 8

typedef unsigned long long ull;

__device__ int    g_off[BATCH + 1];  // prefix sum of ceil(len/64)
__device__ float4 g_E[1024];         // exp(T), lane-coalesced packing

__device__ __forceinline__ float ex2f_(float x) {
    float y; asm("ex2.approx.f32 %0, %1;" : "=f"(y) : "f"(x)); return y;
}
__device__ __forceinline__ float lg2f_(float x) {
    float y; asm("lg2.approx.f32 %0, %1;" : "=f"(y) : "f"(x)); return y;
}
__device__ __forceinline__ ull fma2_(ull a, ull b, ull c) {
    ull d; asm("fma.rn.f32x2 %0, %1, %2, %3;" : "=l"(d) : "l"(a), "l"(b), "l"(c)); return d;
}
__device__ __forceinline__ ull add2_(ull a, ull b) {
    ull d; asm("add.rn.f32x2 %0, %1, %2;" : "=l"(d) : "l"(a), "l"(b)); return d;
}
__device__ __forceinline__ void unpack2_(ull v, float& lo, float& hi) {
    asm("mov.b64 {%0, %1}, %2;" : "=f"(lo), "=f"(hi) : "l"(v));
}

// Compiler-only ordering barrier (validated R16): warp-convergent loop,
// same-warp LSU is in-order, cross-lane STS->LDS kept ordered by ptxas.
#define CBAR() asm volatile("" ::: "memory")

#define MATVEC(BUF)                                                         \
    const ulonglong2* p4_ = (const ulonglong2*)sp[w][BUF];                  \
    ull a0_=0, a1_=0, b0_=0, b1_=0;                                         \
    _Pragma("unroll")                                                       \
    for (int q = 0; q < 16; ++q) {                                          \
        ulonglong2 v_ = p4_[q];                                             \
        a0_ = fma2_(v_.x, EA[2*q],     a0_);                                \
        a1_ = fma2_(v_.y, EA[2*q + 1], a1_);                                \
        b0_ = fma2_(v_.x, EB[2*q],     b0_);                                \
        b1_ = fma2_(v_.y, EB[2*q + 1], b1_);                                \
    }                                                                       \
    float ax_, ay_, bx_, by_;                                               \
    unpack2_(add2_(a0_, a1_), ax_, ay_);                                    \
    unpack2_(add2_(b0_, b1_), bx_, by_);

// FAST step (interior segment): no clamps, no freezes, no compares.
#define STEPF(SLOT, BUF, RENORM) do {                                       \
    float ex_ = er##SLOT.x, ey_ = er##SLOT.y;                               \
    er##SLOT = ts2[(size_t)(s0 + u + 4) * 32 + tid];                        \
    float c0_, c1_;                                                         \
    if (RENORM) {                                                           \
        float p0_ = __shfl_sync(FULL, Px, 0);                               \
        float Kp_ = lg2f_(p0_);                                             \
        c0_ = ex2f_(fmaf(ex_, INV_LN2, -Kp_));                              \
        c1_ = ex2f_(fmaf(ey_, INV_LN2, -Kp_));                              \
        Mcur += Kp_;                                                        \
    } else {                                                                \
        c0_ = ex2f_(ex_ * INV_LN2);                                         \
        c1_ = ex2f_(ey_ * INV_LN2);                                         \
    }                                                                       \
    CBAR();                                                                 \
    { MATVEC(BUF);                                                          \
      Px = (ax_ + ay_) * c0_;  Py = (bx_ + by_) * c1_; }                    \
    ((float2*)sp[w][(BUF) ^ 1])[tid] = make_float2(Px, Py);                 \
    CBAR();                                                                 \
    ++u;                                                                    \
} while (0)

// SLOW step (last segment): clamped prefetch + predicated freeze for pad.
#define STEPS(SLOT, BUF, RENORM) do {                                       \
    float ex_ = er##SLOT.x, ey_ = er##SLOT.y;                               \
    int tt_ = s0 + u + 4; if (tt_ > e) tt_ = e;                             \
    er##SLOT = ts2[(size_t)tt_ * 32 + tid];                                 \
    const bool gg_ = (u <= n);                                              \
    float c0_, c1_;                                                         \
    if (RENORM) {                                                           \
        float p0_ = __shfl_sync(FULL, Px, 0);                               \
        float Kp_ = lg2f_(p0_);                                             \
        c0_ = ex2f_(fmaf(ex_, INV_LN2, -Kp_));                              \
        c1_ = ex2f_(fmaf(ey_, INV_LN2, -Kp_));                              \
        Mcur += gg_ ? Kp_ : 0.0f;                                           \
    } else {                                                                \
        c0_ = ex2f_(ex_ * INV_LN2);                                         \
        c1_ = ex2f_(ey_ * INV_LN2);                                         \
    }                                                                       \
    CBAR();                                                                 \
    { MATVEC(BUF);                                                          \
      float nPx_ = (ax_ + ay_) * c0_;                                       \
      float nPy_ = (bx_ + by_) * c1_;                                       \
      Px = gg_ ? nPx_ : Px;  Py = gg_ ? nPy_ : Py; }                        \
    ((float2*)sp[w][(BUF) ^ 1])[tid] = make_float2(Px, Py);                 \
    CBAR();                                                                 \
    ++u;                                                                    \
} while (0)

#define GROUP8(S) do {                                                      \
    S(0, 0, 1); S(1, 1, 0); S(2, 0, 0); S(3, 1, 0);                         \
    S(0, 0, 0); S(1, 1, 0); S(2, 0, 0); S(3, 1, 0);                         \
} while (0)

// ---- kernel A: prefix-scan of active-segment counts + exp(T) table ----
// g_E[q*32 + l] = (E[2q][2l], E[2q+1][2l], E[2q][2l+1], E[2q+1][2l+1])
__global__ void seg_scan_kernel(const void* __restrict__ lengths_raw,
                                const float* __restrict__ Tm) {
    __shared__ int buf[BATCH];
    const int t = threadIdx.x;
    const int* l32 = (const int*)lengths_raw;
    const bool is64 = (l32[1] == 0);
    int len = is64 ? (int)(((const long long*)lengths_raw)[t]) : l32[t];
    buf[t] = (len + SEGW - 1) >> 6;              // ceil(len/64), >=1

    // E table: 1024 float4 entries, 2 per thread
    #pragma unroll
    for (int r = 0; r < 2; ++r) {
        int idx = t + r * BATCH;                 // 0..1023
        int q = idx >> 5, l = idx & 31;
        float4 v;
        v.x = __expf(Tm[(2*q)     * LBL + 2*l]);
        v.y = __expf(Tm[(2*q + 1) * LBL + 2*l]);
        v.z = __expf(Tm[(2*q)     * LBL + 2*l + 1]);
        v.w = __expf(Tm[(2*q + 1) * LBL + 2*l + 1]);
        g_E[idx] = v;
    }

    __syncthreads();
    for (int d = 1; d < BATCH; d <<= 1) {
        int x = (t >= d) ? buf[t - d] : 0;
        __syncthreads();
        buf[t] += x;
        __syncthreads();
    }
    g_off[t + 1] = buf[t];
    if (t == 0) g_off[0] = 0;
}

// ---- kernel B: compacted work list — global warp W -> (batch b, seg) ----
__global__ __launch_bounds__(128, 2) void crf_loss_kernel(
    const float* __restrict__ ts,          // [B, S, L]
    const float* __restrict__ Tm,          // [L, L]
    const void*  __restrict__ labels_raw,  // [B, S] int32 or int64
    const void*  __restrict__ lengths_raw, // [B]    int32 or int64
    float* __restrict__ out)
{
    const int w   = threadIdx.x >> 5;
    const int tid = threadIdx.x & 31;            // lane: labels 2*tid, 2*tid+1
    const unsigned FULL = 0xffffffffu;

    __shared__ __align__(16) float sp[4][2][LBL];
    __shared__ int soff[BATCH + 1];

    const int total = g_off[BATCH];
    const int Wbase = blockIdx.x << 2;
    if (Wbase >= total) return;                  // whole-CTA early exit

    for (int i = threadIdx.x; i <= BATCH; i += 128) soff[i] = g_off[i];
    __syncthreads();                             // last CTA-wide sync

    const int W = Wbase + w;
    if (W >= total) return;                      // partial CTA: warp exit

    // binary search: b with soff[b] <= W < soff[b+1]
    int blo = 0, bhi = BATCH;
    while (bhi - blo > 1) {
        int mid = (blo + bhi) >> 1;
        if (soff[mid] <= W) blo = mid; else bhi = mid;
    }
    const int b   = blo;
    const int seg = W - soff[b];

    const float INV_LN2 = 1.44269504088896340736f;
    const float LN2     = 0.69314718055994530942f;

    const int* l32 = (const int*)lengths_raw;
    const bool is64 = (l32[1] == 0);
    int len;
    if (is64) len = (int)(((const long long*)lengths_raw)[b]);
    else      len = l32[b];

    const int  tauB = seg * SEGW;
    const int  tauE = tauB + SEGW;
    const bool last = (len <= tauE);

    const float* tsb = ts + (size_t)b * SEQ * LBL;
    const float2* ts2 = (const float2*)tsb;

    // ---- E from the precomputed table: 32 coalesced LDG.128 per lane ----
    ull EA[32], EB[32];
    {
        const ulonglong2* Eg = (const ulonglong2*)g_E;
        #pragma unroll
        for (int q = 0; q < 32; ++q) {
            ulonglong2 v = Eg[q * 32 + tid];
            EA[q] = v.x;                          // (E[2q][2t], E[2q+1][2t])
            EB[q] = v.y;                          // (E[2q][2t+1], E[2q+1][2t+1])
        }
    }

    const int e  = last ? (len - 1) : tauE;
    const int s0 = (seg == 0) ? 0 : (tauB - OV);
    const int n  = e - s0;                       // interior: 72 (seg>0) or 64
    const int ng = (n + 7) >> 3;

    // ---- init A at s0 (true init iff seg0) ----
    float2 a0v = ts2[(size_t)s0 * 32 + tid];
    float A0, A1;
    if (seg == 0) {
        float2 tv = ((const float2*)(Tm + START_ID * LBL))[tid];
        A0 = (a0v.x + tv.x) * INV_LN2;
        A1 = (a0v.y + tv.y) * INV_LN2;
    } else {
        A0 = a0v.x * INV_LN2;
        A1 = a0v.y * INV_LN2;
    }
    float Mcur = __shfl_sync(FULL, A0, 0);
    float Px = ex2f_(A0 - Mcur);
    float Py = ex2f_(A1 - Mcur);
    ((float2*)sp[w][0])[tid] = make_float2(Px, Py);
    CBAR();

    float Msave = Mcur, Psave = Px;

    // ---- named-register prefetch ring (depth 4) ----
    float2 er0, er1, er2, er3;
    {
        int t1 = s0 + 1; if (t1 > e) t1 = e;
        int t2 = s0 + 2; if (t2 > e) t2 = e;
        int t3 = s0 + 3; if (t3 > e) t3 = e;
        int t4 = s0 + 4; if (t4 > e) t4 = e;
        er0 = ts2[(size_t)t1 * 32 + tid];
        er1 = ts2[(size_t)t2 * 32 + tid];
        er2 = ts2[(size_t)t3 * 32 + tid];
        er3 = ts2[(size_t)t4 * 32 + tid];
    }

    int u = 1;
    if (ng > 0) {
        if (!last) {
            GROUP8(STEPF);
            if (seg) { Msave = Mcur; Psave = Px; }   // u==8==OV: V(tauB) snapshot
            for (int g = 1; g < ng; ++g) GROUP8(STEPF);
        } else {
            GROUP8(STEPS);
            if (seg) { Msave = Mcur; Psave = Px; }
            for (int g = 1; g < ng; ++g) GROUP8(STEPS);
        }
    }

    // ---- segment contribution (log2 units) ----
    float fwd;
    if (last) {
        float tp0 = Tm[(2*tid)     * LBL + PAD_ID] * INV_LN2;
        float tp1 = Tm[(2*tid + 1) * LBL + PAD_ID] * INV_LN2;
        float z0 = Mcur + lg2f_(Px) + tp0;
        float z1 = Mcur + lg2f_(Py) + tp1;
        float m = fmaxf(z0, z1);
        #pragma unroll
        for (int o = 16; o > 0; o >>= 1)
            m = fmaxf(m, __shfl_xor_sync(FULL, m, o));
        float sv = ex2f_(z0 - m) + ex2f_(z1 - m);
        #pragma unroll
        for (int o = 16; o > 0; o >>= 1)
            sv += __shfl_xor_sync(FULL, sv, o);
        fwd = m + lg2f_(sv);
    } else {
        float pe0 = __shfl_sync(FULL, Px, 0);
        fwd = Mcur + lg2f_(pe0);                 // +V(tauE)
    }
    if (seg > 0) {
        float ps0 = __shfl_sync(FULL, Psave, 0);
        fwd -= (Msave + lg2f_(ps0));             // -V(tauB)
    }

    // ---- gold path score over [tauB, min(tauE, len)) ----
    const int hi = last ? len : tauE;
    float gsum = 0.0f;
    int last_label = 0;
    if (is64) {
        const long long* lab = (const long long*)labels_raw + (size_t)b * SEQ;
        for (int t = tauB + tid; t < hi; t += 32) {
            int lt = (int)lab[t];
            int pt = (t == 0) ? START_ID : (int)lab[t - 1];
            gsum += Tm[pt * LBL + lt] + tsb[(size_t)t * LBL + lt];
        }
        if (last && tid == 0) last_label = (int)lab[len - 1];
    } else {
        const int* lab = (const int*)labels_raw + (size_t)b * SEQ;
        for (int t = tauB + tid; t < hi; t += 32) {
            int lt = lab[t];
            int pt = (t == 0) ? START_ID : lab[t - 1];
            gsum += Tm[pt * LBL + lt] + tsb[(size_t)t * LBL + lt];
        }
        if (last && tid == 0) last_label = lab[len - 1];
    }
    #pragma unroll
    for (int o = 16; o > 0; o >>= 1)
        gsum += __shfl_xor_sync(FULL, gsum, o);

    if (tid == 0) {
        float gold = gsum + (last ? Tm[last_label * LBL + PAD_ID] : 0.0f);
        atomicAdd(out, (fwd * LN2 - gold) * (1.0f / (float)BATCH));
    }
}

extern "C" void kernel_launch(void* const* d_in, const int* in_sizes, int n_in,
                              void* d_out, int out_size)
{
    const float* ts      = (const float*)d_in[0];
    const float* Tm      = (const float*)d_in[1];
    const void*  labels  = d_in[2];
    const void*  lengths = d_in[3];
    float* out = (float*)d_out;

    cudaMemsetAsync(out, 0, sizeof(float));
    seg_scan_kernel<<<1, BATCH>>>(lengths, Tm);
    // max possible works = BATCH * 8; trailing CTAs exit immediately
    crf_loss_kernel<<<(BATCH * 8) / 4, 128>>>(ts, Tm, labels, lengths, out);
}